// round 14
// baseline (speedup 1.0000x reference)
#include <cuda_runtime.h>
#include <cuda_bf16.h>
#include <cstdint>

#define NMAX 50000
#define NPAD 53248
#define EMAX 800000
#define DF   128

__device__ int   g_cnt[NPAD];             // zero-init at load; re-zeroed by scatter
__device__ int   g_off[NMAX + 4];
__device__ int   g_cur[NMAX + 4];
__device__ int2  g_edge[EMAX];
__device__ float g_sum[DF];
__device__ float g_sumsq[DF];
__device__ unsigned g_bar;

// ===========================================================================
// 1) Histogram of dst (g_cnt pre-zeroed: static init / previous scatter)
// ===========================================================================
__global__ void hist_kernel(const int* __restrict__ dst, int E) {
    int i4 = (blockIdx.x * blockDim.x + threadIdx.x) * 4;
    if (i4 + 3 < E) {
        int4 d = *reinterpret_cast<const int4*>(dst + i4);
        atomicAdd(&g_cnt[d.x], 1);
        atomicAdd(&g_cnt[d.y], 1);
        atomicAdd(&g_cnt[d.z], 1);
        atomicAdd(&g_cnt[d.w], 1);
    } else {
        for (int i = i4; i < E; i++) atomicAdd(&g_cnt[dst[i]], 1);
    }
}

// ===========================================================================
// 2) Exclusive scan (also zeroes BN stats + grid barrier for this launch)
// ===========================================================================
__global__ __launch_bounds__(1024, 1)
void scan_kernel(int N) {
    __shared__ int wsum[32];
    __shared__ int s_carry;
    const int tid = threadIdx.x;
    const int lane = tid & 31, wid = tid >> 5;
    if (tid < DF) { g_sum[tid] = 0.f; g_sumsq[tid] = 0.f; }
    if (tid == 0) { g_bar = 0; s_carry = 0; }
    __syncthreads();
    const int CH = 4096;
    for (int base = 0; base < N; base += CH) {
        int i0 = base + tid * 4;
        int4 v = *reinterpret_cast<const int4*>(&g_cnt[i0]);
        int s0 = v.x, s1 = s0 + v.y, s2 = s1 + v.z, s3 = s2 + v.w;
        int x = s3;
#pragma unroll
        for (int o = 1; o < 32; o <<= 1) {
            int y = __shfl_up_sync(0xFFFFFFFFu, x, o);
            if (lane >= o) x += y;
        }
        if (lane == 31) wsum[wid] = x;
        __syncthreads();
        if (wid == 0) {
            int s = wsum[lane];
#pragma unroll
            for (int o = 1; o < 32; o <<= 1) {
                int y = __shfl_up_sync(0xFFFFFFFFu, s, o);
                if (lane >= o) s += y;
            }
            wsum[lane] = s;
        }
        __syncthreads();
        int we = (wid == 0) ? 0 : wsum[wid - 1];
        int excl = s_carry + we + x - s3;
        if (i0 < N) {
            int4 off = make_int4(excl, excl + s0, excl + s1, excl + s2);
            *reinterpret_cast<int4*>(&g_off[i0]) = off;
            *reinterpret_cast<int4*>(&g_cur[i0]) = off;
        }
        int chunk_total = wsum[31];
        __syncthreads();
        if (tid == 0) s_carry += chunk_total;
        __syncthreads();
    }
    if (tid == 0) g_off[N] = s_carry;
}

// ===========================================================================
// 3) Scatter edges into CSR order + re-zero g_cnt for the next launch
// ===========================================================================
__global__ void scatter_kernel(const int* __restrict__ src,
                               const int* __restrict__ dst,
                               const float* __restrict__ ew,
                               int E) {
    int i = blockIdx.x * blockDim.x + threadIdx.x;
    if (i < NPAD) g_cnt[i] = 0;              // scan already consumed g_cnt
    if (i < E) {
        int d = dst[i];
        int pos = atomicAdd(&g_cur[d], 1);
        g_edge[pos] = make_int2(src[i], __float_as_int(ew[i]));
    }
}

// ===========================================================================
// 4) Persistent fused kernel: CSR gather-aggregate -> split-bf16 mma.sync
//    GEMM -> bias+ReLU -> BN stats -> grid barrier -> BN normalize.
//    Block tile 64 rows x 128 cols; 8 warps = 2(m) x 4(n); warp tile 32x32.
//    3 passes: Ahi*Whi + Ahi*Wlo + Alo*Whi, fp32 accumulate.
// ===========================================================================
#define TILE_M 64
#define GRID_GEMM 148
#define SM_WHI  0
#define SM_WLO  65536
#define SM_AHI  131072
#define SM_ALO  163840
#define SM_BC   196608
#define SM_SSUM 197120
#define SM_SSQ  197632
#define SMEM_GEMM_BYTES 198272

__device__ __forceinline__ uint32_t smem_u32(const void* p) {
    uint32_t a;
    asm("{ .reg .u64 t; cvta.to.shared.u64 t, %1; cvt.u32.u64 %0, t; }"
        : "=r"(a) : "l"(p));
    return a;
}
__device__ __forceinline__ void ldsm4(uint32_t& r0, uint32_t& r1,
                                      uint32_t& r2, uint32_t& r3, uint32_t addr) {
    asm volatile("ldmatrix.sync.aligned.m8n8.x4.shared.b16 {%0,%1,%2,%3}, [%4];"
                 : "=r"(r0), "=r"(r1), "=r"(r2), "=r"(r3) : "r"(addr));
}
__device__ __forceinline__ void mma16816(float* d, uint32_t a0, uint32_t a1,
                                         uint32_t a2, uint32_t a3,
                                         uint32_t b0, uint32_t b1) {
    asm volatile(
        "mma.sync.aligned.m16n8k16.row.col.f32.bf16.bf16.f32 "
        "{%0,%1,%2,%3}, {%4,%5,%6,%7}, {%8,%9}, {%0,%1,%2,%3};"
        : "+f"(d[0]), "+f"(d[1]), "+f"(d[2]), "+f"(d[3])
        : "r"(a0), "r"(a1), "r"(a2), "r"(a3), "r"(b0), "r"(b1));
}
__device__ __forceinline__ uint32_t packbf2(float a, float b) {
    __nv_bfloat16 h0 = __float2bfloat16_rn(a);
    __nv_bfloat16 h1 = __float2bfloat16_rn(b);
    return (uint32_t)__bfloat16_as_ushort(h0)
         | ((uint32_t)__bfloat16_as_ushort(h1) << 16);
}
__device__ __forceinline__ void cvt8(const float* f, uint4& hi, uint4& lo) {
    uint32_t h[4], l[4];
#pragma unroll
    for (int i = 0; i < 4; i++) {
        __nv_bfloat16 h0 = __float2bfloat16_rn(f[2 * i]);
        __nv_bfloat16 h1 = __float2bfloat16_rn(f[2 * i + 1]);
        h[i] = (uint32_t)__bfloat16_as_ushort(h0)
             | ((uint32_t)__bfloat16_as_ushort(h1) << 16);
        l[i] = packbf2(f[2 * i] - __bfloat162float(h0),
                       f[2 * i + 1] - __bfloat162float(h1));
    }
    hi = make_uint4(h[0], h[1], h[2], h[3]);
    lo = make_uint4(l[0], l[1], l[2], l[3]);
}

__global__ __launch_bounds__(256, 1)
void gemm_kernel(const float* __restrict__ feat,
                 const float* __restrict__ Wneigh,
                 const float* __restrict__ Wself,
                 const float* __restrict__ b_self,
                 const float* __restrict__ bias,
                 const float* __restrict__ gamma,
                 const float* __restrict__ beta,
                 float* __restrict__ out,
                 int N) {
    extern __shared__ char sm[];
    float* s_bc   = reinterpret_cast<float*>(sm + SM_BC);
    float* s_ssum = reinterpret_cast<float*>(sm + SM_SSUM);
    float* s_ssq  = reinterpret_cast<float*>(sm + SM_SSQ);

    const int tid = threadIdx.x;
    const int lane = tid & 31;
    const int wid = tid >> 5;
    const int wm = wid & 1;
    const int wn = wid >> 1;
    const int l7 = lane & 7;
    const int l15 = lane & 15;
    const int lh = lane >> 4;
    const int bkh = (lane >> 3) & 1;
    const int bn = ((lane >> 4) << 3) | l7;

    const uint32_t sb = smem_u32(sm);

    // ---- W hi/lo fill (once) ----
    for (int idx = tid; idx < 128 * 32; idx += 256) {
        int n = idx >> 5;
        int u = idx & 31;
        int k = u * 8;
        float f[8];
        const float* p = (k < DF) ? (Wself + n * DF + k)
                                  : (Wneigh + n * DF + (k - DF));
        *reinterpret_cast<float4*>(f)     = *reinterpret_cast<const float4*>(p);
        *reinterpret_cast<float4*>(f + 4) = *reinterpret_cast<const float4*>(p + 4);
        uint4 hi, lo;
        cvt8(f, hi, lo);
        uint32_t off = n * 512 + ((u ^ (n & 7)) * 16);
        *reinterpret_cast<uint4*>(sm + SM_WHI + off) = hi;
        *reinterpret_cast<uint4*>(sm + SM_WLO + off) = lo;
    }
    if (tid < DF) {
        s_bc[tid] = __ldg(&b_self[tid]) + __ldg(&bias[tid]);
        s_ssum[tid] = 0.f;
        s_ssq[tid] = 0.f;
    }
    __syncthreads();

    uint32_t rowA[2], rowB[2];
#pragma unroll
    for (int mi = 0; mi < 2; mi++)
        rowA[mi] = (uint32_t)(wm * 32 + mi * 16 + l15) * 512;
#pragma unroll
    for (int gi = 0; gi < 2; gi++)
        rowB[gi] = (uint32_t)(wn * 32 + gi * 16 + bn) * 512;

    // Agg write offsets for this lane: elements k = 128 + lane*4 .. +3
    // unit u = 16 + (lane>>1); within-unit byte = (lane&1)*8
    const uint32_t agg_u = 16 + (lane >> 1);
    const uint32_t agg_sub = (lane & 1) * 8;

    float st_s[8], st_q[8];
#pragma unroll
    for (int i = 0; i < 8; i++) { st_s[i] = 0.f; st_q[i] = 0.f; }

    const int ntiles = (N + TILE_M - 1) / TILE_M;

    for (int tile = blockIdx.x; tile < ntiles; tile += gridDim.x) {
        const int row0 = tile * TILE_M;

        __syncthreads();   // prior tile's ldmatrix reads done

        // ---- Fused aggregation: warp w handles rows w*8 .. w*8+7 ----
#pragma unroll 1
        for (int i = 0; i < 8; i++) {
            int r = wid * 8 + i;
            int node = row0 + r;
            float4 acc = make_float4(0.f, 0.f, 0.f, 0.f);
            float deg = 0.f;
            if (node < N) {
                int beg = __ldg(&g_off[node]);
                int end = __ldg(&g_off[node + 1]);
#pragma unroll 2
                for (int e = beg; e < end; e++) {
                    int2 ed = __ldg(&g_edge[e]);
                    float w = __int_as_float(ed.y);
                    const float4 v = *reinterpret_cast<const float4*>(
                        feat + (size_t)ed.x * DF + lane * 4);
                    acc.x = fmaf(v.x, w, acc.x);
                    acc.y = fmaf(v.y, w, acc.y);
                    acc.z = fmaf(v.z, w, acc.z);
                    acc.w = fmaf(v.w, w, acc.w);
                    deg += w;
                }
                float inv = 1.0f / (deg + 1e-8f);
                acc.x *= inv; acc.y *= inv; acc.z *= inv; acc.w *= inv;
            }
            // direct bf16 hi/lo store into swizzled A tile (neigh half)
            uint32_t off = (uint32_t)r * 512 + ((agg_u ^ (uint32_t)(r & 7)) * 16)
                         + agg_sub;
            uint32_t h0 = packbf2(acc.x, acc.y);
            uint32_t h1 = packbf2(acc.z, acc.w);
            *reinterpret_cast<uint2*>(sm + SM_AHI + off) = make_uint2(h0, h1);
            uint32_t l0 = packbf2(acc.x - __bfloat162float(__ushort_as_bfloat16(h0 & 0xFFFF)),
                                  acc.y - __bfloat162float(__ushort_as_bfloat16(h0 >> 16)));
            uint32_t l1 = packbf2(acc.z - __bfloat162float(__ushort_as_bfloat16(h1 & 0xFFFF)),
                                  acc.w - __bfloat162float(__ushort_as_bfloat16(h1 >> 16)));
            *reinterpret_cast<uint2*>(sm + SM_ALO + off) = make_uint2(l0, l1);
        }

        // ---- Feat half of A tile: 64 rows x 16 units ----
        for (int idx = tid; idx < TILE_M * 16; idx += 256) {
            int r = idx >> 4;
            int u = idx & 15;
            uint32_t off = r * 512 + ((u ^ (r & 7)) * 16);
            if (row0 + r < N) {
                const float* p = feat + (size_t)(row0 + r) * DF + u * 8;
                float f[8];
                *reinterpret_cast<float4*>(f)     = *reinterpret_cast<const float4*>(p);
                *reinterpret_cast<float4*>(f + 4) = *reinterpret_cast<const float4*>(p + 4);
                uint4 hi, lo;
                cvt8(f, hi, lo);
                *reinterpret_cast<uint4*>(sm + SM_AHI + off) = hi;
                *reinterpret_cast<uint4*>(sm + SM_ALO + off) = lo;
            } else {
                uint4 z = make_uint4(0, 0, 0, 0);
                *reinterpret_cast<uint4*>(sm + SM_AHI + off) = z;
                *reinterpret_cast<uint4*>(sm + SM_ALO + off) = z;
            }
        }
        __syncthreads();

        float d[2][4][4];
#pragma unroll
        for (int mi = 0; mi < 2; mi++)
#pragma unroll
            for (int t = 0; t < 4; t++)
#pragma unroll
                for (int i = 0; i < 4; i++) d[mi][t][i] = 0.f;

#pragma unroll
        for (int pass = 0; pass < 3; pass++) {
            const uint32_t Ab = sb + ((pass == 2) ? SM_ALO : SM_AHI);
            const uint32_t Wb = sb + ((pass == 1) ? SM_WLO : SM_WHI);
#pragma unroll
            for (int kq = 0; kq < 16; kq++) {
                uint32_t a[2][4], b[2][4];
                uint32_t ua = (uint32_t)(((2 * kq + lh) ^ l7) * 16);
                uint32_t ub = (uint32_t)(((2 * kq + bkh) ^ l7) * 16);
#pragma unroll
                for (int mi = 0; mi < 2; mi++)
                    ldsm4(a[mi][0], a[mi][1], a[mi][2], a[mi][3],
                          Ab + rowA[mi] + ua);
#pragma unroll
                for (int gi = 0; gi < 2; gi++)
                    ldsm4(b[gi][0], b[gi][1], b[gi][2], b[gi][3],
                          Wb + rowB[gi] + ub);
#pragma unroll
                for (int mi = 0; mi < 2; mi++)
#pragma unroll
                    for (int gi = 0; gi < 2; gi++) {
                        mma16816(d[mi][gi * 2 + 0], a[mi][0], a[mi][1],
                                 a[mi][2], a[mi][3], b[gi][0], b[gi][1]);
                        mma16816(d[mi][gi * 2 + 1], a[mi][0], a[mi][1],
                                 a[mi][2], a[mi][3], b[gi][2], b[gi][3]);
                    }
            }
        }

        // ---- Epilogue: bias + ReLU + store + BN stats ----
#pragma unroll
        for (int mi = 0; mi < 2; mi++) {
            int r0g = row0 + wm * 32 + mi * 16 + (lane >> 2);
            int r1g = r0g + 8;
            bool v0 = r0g < N, v1 = r1g < N;
#pragma unroll
            for (int t = 0; t < 4; t++) {
                int cb = wn * 32 + t * 8 + (lane & 3) * 2;
                float x0 = fmaxf(d[mi][t][0] + s_bc[cb],     0.f);
                float x1 = fmaxf(d[mi][t][1] + s_bc[cb + 1], 0.f);
                float x2 = fmaxf(d[mi][t][2] + s_bc[cb],     0.f);
                float x3 = fmaxf(d[mi][t][3] + s_bc[cb + 1], 0.f);
                if (v0) {
                    *reinterpret_cast<float2*>(&out[(size_t)r0g * DF + cb]) =
                        make_float2(x0, x1);
                    st_s[t * 2]     += x0; st_q[t * 2]     += x0 * x0;
                    st_s[t * 2 + 1] += x1; st_q[t * 2 + 1] += x1 * x1;
                }
                if (v1) {
                    *reinterpret_cast<float2*>(&out[(size_t)r1g * DF + cb]) =
                        make_float2(x2, x3);
                    st_s[t * 2]     += x2; st_q[t * 2]     += x2 * x2;
                    st_s[t * 2 + 1] += x3; st_q[t * 2 + 1] += x3 * x3;
                }
            }
        }
    }

    // ---- Flush BN stats: registers -> shared -> global ----
#pragma unroll
    for (int t = 0; t < 4; t++)
#pragma unroll
        for (int c = 0; c < 2; c++) {
            int col = wn * 32 + t * 8 + (lane & 3) * 2 + c;
            atomicAdd(&s_ssum[col], st_s[t * 2 + c]);
            atomicAdd(&s_ssq[col], st_q[t * 2 + c]);
        }
    __syncthreads();
    if (tid < DF) {
        atomicAdd(&g_sum[tid], s_ssum[tid]);
        atomicAdd(&g_sumsq[tid], s_ssq[tid]);
    }

    // ---- Grid-wide barrier (148 blocks, 1/SM resident) ----
    __threadfence();
    __syncthreads();
    if (tid == 0) {
        atomicAdd(&g_bar, 1u);
        while (atomicAdd(&g_bar, 0u) < (unsigned)gridDim.x) __nanosleep(64);
    }
    __syncthreads();
    __threadfence();

    // ---- BN scale/shift (reuse ssum/ssq smem) ----
    if (tid < DF) {
        float invn = 1.0f / (float)N;
        float mu = __ldcg(&g_sum[tid]) * invn;
        float var = __ldcg(&g_sumsq[tid]) * invn - mu * mu;
        float rs = rsqrtf(var + 1e-5f);
        float s = gamma[tid] * rs;
        s_ssum[tid] = s;                       // scale
        s_ssq[tid] = beta[tid] - mu * s;       // shift
    }
    __syncthreads();

    for (int tile = blockIdx.x; tile < ntiles; tile += gridDim.x) {
        const int row0 = tile * TILE_M;
        const int rows = min(TILE_M, N - row0);
        for (int idx = tid; idx < rows * 32; idx += 256) {
            int r = idx >> 5;
            int c4 = (idx & 31) * 4;
            float4* p = reinterpret_cast<float4*>(
                &out[(size_t)(row0 + r) * DF + c4]);
            float4 v = *p;
            float4 s = *reinterpret_cast<float4*>(&s_ssum[c4]);
            float4 h = *reinterpret_cast<float4*>(&s_ssq[c4]);
            v.x = v.x * s.x + h.x;
            v.y = v.y * s.y + h.y;
            v.z = v.z * s.z + h.z;
            v.w = v.w * s.w + h.w;
            *p = v;
        }
    }
}

// ===========================================================================
// Launch
// ===========================================================================
extern "C" void kernel_launch(void* const* d_in, const int* in_sizes, int n_in,
                              void* d_out, int out_size) {
    const float* feat   = (const float*)d_in[0];
    const int*   src    = (const int*)  d_in[1];
    const int*   dst    = (const int*)  d_in[2];
    const float* ew     = (const float*)d_in[3];
    const float* Wneigh = (const float*)d_in[4];
    const float* Wself  = (const float*)d_in[5];
    const float* b_self = (const float*)d_in[6];
    const float* bias   = (const float*)d_in[7];
    const float* gamma  = (const float*)d_in[8];
    const float* beta   = (const float*)d_in[9];
    float* out = (float*)d_out;

    const int N = in_sizes[0] / DF;
    const int E = in_sizes[1];

    cudaFuncSetAttribute(gemm_kernel,
                         cudaFuncAttributeMaxDynamicSharedMemorySize,
                         SMEM_GEMM_BYTES);

    hist_kernel<<<(E / 4 + 255) / 256, 256>>>(dst, E);
    scan_kernel<<<1, 1024>>>(N);
    scatter_kernel<<<(E + 255) / 256, 256>>>(src, dst, ew, E);
    gemm_kernel<<<GRID_GEMM, 256, SMEM_GEMM_BYTES>>>(feat, Wneigh, Wself, b_self,
                                                     bias, gamma, beta, out, N);
}

// round 15
// speedup vs baseline: 1.4961x; 1.4961x over previous
#include <cuda_runtime.h>
#include <cuda_bf16.h>
#include <cstdint>

#define NMAX 50000
#define NPAD 53248
#define EMAX 800000
#define DF   128

__device__ int   g_cnt[NPAD];             // zero-init at load; re-zeroed by scatter
__device__ int   g_off[NMAX + 4];
__device__ int   g_cur[NMAX + 4];
__device__ int2  g_edge[EMAX];
__device__ uint2 g_nhi[NMAX * 32];        // neigh mean, bf16 hi, packed 4 floats/lane
__device__ uint2 g_nlo[NMAX * 32];        // neigh mean, bf16 lo residual
__device__ float g_sum[DF];
__device__ float g_sumsq[DF];
__device__ unsigned g_bar;

// ===========================================================================
// helpers
// ===========================================================================
__device__ __forceinline__ uint32_t smem_u32(const void* p) {
    uint32_t a;
    asm("{ .reg .u64 t; cvta.to.shared.u64 t, %1; cvt.u32.u64 %0, t; }"
        : "=r"(a) : "l"(p));
    return a;
}
__device__ __forceinline__ void ldsm4(uint32_t& r0, uint32_t& r1,
                                      uint32_t& r2, uint32_t& r3, uint32_t addr) {
    asm volatile("ldmatrix.sync.aligned.m8n8.x4.shared.b16 {%0,%1,%2,%3}, [%4];"
                 : "=r"(r0), "=r"(r1), "=r"(r2), "=r"(r3) : "r"(addr));
}
__device__ __forceinline__ void mma16816(float* d, uint32_t a0, uint32_t a1,
                                         uint32_t a2, uint32_t a3,
                                         uint32_t b0, uint32_t b1) {
    asm volatile(
        "mma.sync.aligned.m16n8k16.row.col.f32.bf16.bf16.f32 "
        "{%0,%1,%2,%3}, {%4,%5,%6,%7}, {%8,%9}, {%0,%1,%2,%3};"
        : "+f"(d[0]), "+f"(d[1]), "+f"(d[2]), "+f"(d[3])
        : "r"(a0), "r"(a1), "r"(a2), "r"(a3), "r"(b0), "r"(b1));
}
__device__ __forceinline__ uint32_t packbf2(float a, float b) {
    __nv_bfloat16 h0 = __float2bfloat16_rn(a);
    __nv_bfloat16 h1 = __float2bfloat16_rn(b);
    return (uint32_t)__bfloat16_as_ushort(h0)
         | ((uint32_t)__bfloat16_as_ushort(h1) << 16);
}
__device__ __forceinline__ void cvt8(const float* f, uint4& hi, uint4& lo) {
    uint32_t h[4], l[4];
#pragma unroll
    for (int i = 0; i < 4; i++) {
        __nv_bfloat16 h0 = __float2bfloat16_rn(f[2 * i]);
        __nv_bfloat16 h1 = __float2bfloat16_rn(f[2 * i + 1]);
        h[i] = (uint32_t)__bfloat16_as_ushort(h0)
             | ((uint32_t)__bfloat16_as_ushort(h1) << 16);
        l[i] = packbf2(f[2 * i] - __bfloat162float(h0),
                       f[2 * i + 1] - __bfloat162float(h1));
    }
    hi = make_uint4(h[0], h[1], h[2], h[3]);
    lo = make_uint4(l[0], l[1], l[2], l[3]);
}

// ===========================================================================
// 1) Histogram of dst (g_cnt pre-zeroed: static init / previous scatter)
// ===========================================================================
__global__ void hist_kernel(const int* __restrict__ dst, int E) {
    int i4 = (blockIdx.x * blockDim.x + threadIdx.x) * 4;
    if (i4 + 3 < E) {
        int4 d = *reinterpret_cast<const int4*>(dst + i4);
        atomicAdd(&g_cnt[d.x], 1);
        atomicAdd(&g_cnt[d.y], 1);
        atomicAdd(&g_cnt[d.z], 1);
        atomicAdd(&g_cnt[d.w], 1);
    } else {
        for (int i = i4; i < E; i++) atomicAdd(&g_cnt[dst[i]], 1);
    }
}

// ===========================================================================
// 2) Exclusive scan (also zeroes BN stats + grid barrier for this launch)
// ===========================================================================
__global__ __launch_bounds__(1024, 1)
void scan_kernel(int N) {
    __shared__ int wsum[32];
    __shared__ int s_carry;
    const int tid = threadIdx.x;
    const int lane = tid & 31, wid = tid >> 5;
    if (tid < DF) { g_sum[tid] = 0.f; g_sumsq[tid] = 0.f; }
    if (tid == 0) { g_bar = 0; s_carry = 0; }
    __syncthreads();
    const int CH = 4096;
    for (int base = 0; base < N; base += CH) {
        int i0 = base + tid * 4;
        int4 v = *reinterpret_cast<const int4*>(&g_cnt[i0]);
        int s0 = v.x, s1 = s0 + v.y, s2 = s1 + v.z, s3 = s2 + v.w;
        int x = s3;
#pragma unroll
        for (int o = 1; o < 32; o <<= 1) {
            int y = __shfl_up_sync(0xFFFFFFFFu, x, o);
            if (lane >= o) x += y;
        }
        if (lane == 31) wsum[wid] = x;
        __syncthreads();
        if (wid == 0) {
            int s = wsum[lane];
#pragma unroll
            for (int o = 1; o < 32; o <<= 1) {
                int y = __shfl_up_sync(0xFFFFFFFFu, s, o);
                if (lane >= o) s += y;
            }
            wsum[lane] = s;
        }
        __syncthreads();
        int we = (wid == 0) ? 0 : wsum[wid - 1];
        int excl = s_carry + we + x - s3;
        if (i0 < N) {
            int4 off = make_int4(excl, excl + s0, excl + s1, excl + s2);
            *reinterpret_cast<int4*>(&g_off[i0]) = off;
            *reinterpret_cast<int4*>(&g_cur[i0]) = off;
        }
        int chunk_total = wsum[31];
        __syncthreads();
        if (tid == 0) s_carry += chunk_total;
        __syncthreads();
    }
    if (tid == 0) g_off[N] = s_carry;
}

// ===========================================================================
// 3) Scatter edges into CSR order + re-zero g_cnt for the next launch
// ===========================================================================
__global__ void scatter_kernel(const int* __restrict__ src,
                               const int* __restrict__ dst,
                               const float* __restrict__ ew,
                               int E) {
    int i = blockIdx.x * blockDim.x + threadIdx.x;
    if (i < NPAD) g_cnt[i] = 0;
    if (i < E) {
        int d = dst[i];
        int pos = atomicAdd(&g_cur[d], 1);
        g_edge[pos] = make_int2(src[i], __float_as_int(ew[i]));
    }
}

// ===========================================================================
// 4) Gather-aggregate: one warp per node, emits packed bf16 hi/lo mean
// ===========================================================================
__global__ void agg_kernel(const float* __restrict__ feat, int N) {
    int node = (blockIdx.x * blockDim.x + threadIdx.x) >> 5;
    int lane = threadIdx.x & 31;
    if (node >= N) return;
    int beg = g_off[node];
    int end = g_off[node + 1];
    float4 acc = make_float4(0.f, 0.f, 0.f, 0.f);
    float deg = 0.f;
    for (int e = beg; e < end; e++) {
        int2 ed = __ldg(&g_edge[e]);
        float w = __int_as_float(ed.y);
        const float4 v = *reinterpret_cast<const float4*>(
            feat + (size_t)ed.x * DF + lane * 4);
        acc.x = fmaf(v.x, w, acc.x);
        acc.y = fmaf(v.y, w, acc.y);
        acc.z = fmaf(v.z, w, acc.z);
        acc.w = fmaf(v.w, w, acc.w);
        deg += w;
    }
    float inv = 1.0f / (deg + 1e-8f);
    acc.x *= inv; acc.y *= inv; acc.z *= inv; acc.w *= inv;
    uint32_t h0 = packbf2(acc.x, acc.y);
    uint32_t h1 = packbf2(acc.z, acc.w);
    g_nhi[node * 32 + lane] = make_uint2(h0, h1);
    uint32_t l0 = packbf2(acc.x - __bfloat162float(__ushort_as_bfloat16(h0 & 0xFFFF)),
                          acc.y - __bfloat162float(__ushort_as_bfloat16(h0 >> 16)));
    uint32_t l1 = packbf2(acc.z - __bfloat162float(__ushort_as_bfloat16(h1 & 0xFFFF)),
                          acc.w - __bfloat162float(__ushort_as_bfloat16(h1 >> 16)));
    g_nlo[node * 32 + lane] = make_uint2(l0, l1);
}

// ===========================================================================
// 5) Persistent split-bf16 mma.sync GEMM + bias + ReLU + BN stats
//    + grid barrier + BN normalize.
//    512 threads; block tile 64x128; warp grid 4(m)x4(n); warp tile 16x32.
// ===========================================================================
#define TILE_M 64
#define GRID_GEMM 148
#define NTHREADS 512
#define SM_WHI  0
#define SM_WLO  65536
#define SM_AHI  131072
#define SM_ALO  163840
#define SM_BC   196608
#define SM_SSUM 197120
#define SM_SSQ  197632
#define SMEM_GEMM_BYTES 198272

__global__ __launch_bounds__(NTHREADS, 1)
void gemm_kernel(const float* __restrict__ feat,
                 const float* __restrict__ Wneigh,
                 const float* __restrict__ Wself,
                 const float* __restrict__ b_self,
                 const float* __restrict__ bias,
                 const float* __restrict__ gamma,
                 const float* __restrict__ beta,
                 float* __restrict__ out,
                 int N) {
    extern __shared__ char sm[];
    float* s_bc   = reinterpret_cast<float*>(sm + SM_BC);
    float* s_ssum = reinterpret_cast<float*>(sm + SM_SSUM);
    float* s_ssq  = reinterpret_cast<float*>(sm + SM_SSQ);

    const int tid = threadIdx.x;
    const int lane = tid & 31;
    const int wid = tid >> 5;
    const int wm = wid & 3;          // 0..3 : rows wm*16..wm*16+15
    const int wn = wid >> 2;         // 0..3 : cols wn*32..wn*32+31
    const int l7 = lane & 7;
    const int l15 = lane & 15;
    const int lh = lane >> 4;        // A k-half
    const int bkh = (lane >> 3) & 1; // B k-half
    const int bn = ((lane >> 4) << 3) | l7;

    const uint32_t sb = smem_u32(sm);

    // ---- W hi/lo fill (once) ----
    for (int idx = tid; idx < 128 * 32; idx += NTHREADS) {
        int n = idx >> 5;
        int u = idx & 31;
        int k = u * 8;
        float f[8];
        const float* p = (k < DF) ? (Wself + n * DF + k)
                                  : (Wneigh + n * DF + (k - DF));
        *reinterpret_cast<float4*>(f)     = *reinterpret_cast<const float4*>(p);
        *reinterpret_cast<float4*>(f + 4) = *reinterpret_cast<const float4*>(p + 4);
        uint4 hi, lo;
        cvt8(f, hi, lo);
        uint32_t off = n * 512 + ((u ^ (n & 7)) * 16);
        *reinterpret_cast<uint4*>(sm + SM_WHI + off) = hi;
        *reinterpret_cast<uint4*>(sm + SM_WLO + off) = lo;
    }
    if (tid < DF) {
        s_bc[tid] = __ldg(&b_self[tid]) + __ldg(&bias[tid]);
        s_ssum[tid] = 0.f;
        s_ssq[tid] = 0.f;
    }
    __syncthreads();

    const uint32_t rowA = (uint32_t)(wm * 16 + l15) * 512;
    uint32_t rowB[2];
#pragma unroll
    for (int gi = 0; gi < 2; gi++)
        rowB[gi] = (uint32_t)(wn * 32 + gi * 16 + bn) * 512;

    float st_s[8], st_q[8];
#pragma unroll
    for (int i = 0; i < 8; i++) { st_s[i] = 0.f; st_q[i] = 0.f; }

    const int ntiles = (N + TILE_M - 1) / TILE_M;

    for (int tile = blockIdx.x; tile < ntiles; tile += gridDim.x) {
        const int row0 = tile * TILE_M;

        __syncthreads();   // prior tile's ldmatrix reads done

        // ---- A tile fill: feat half converts, neigh half copies ----
        for (int idx = tid; idx < TILE_M * 16; idx += NTHREADS) {
            int r = idx >> 4;
            int u = idx & 15;
            int node = row0 + r;
            // feat half (units 0..15)
            {
                uint32_t off = r * 512 + ((u ^ (r & 7)) * 16);
                if (node < N) {
                    const float* p = feat + (size_t)node * DF + u * 8;
                    float f[8];
                    *reinterpret_cast<float4*>(f)     = *reinterpret_cast<const float4*>(p);
                    *reinterpret_cast<float4*>(f + 4) = *reinterpret_cast<const float4*>(p + 4);
                    uint4 hi, lo;
                    cvt8(f, hi, lo);
                    *reinterpret_cast<uint4*>(sm + SM_AHI + off) = hi;
                    *reinterpret_cast<uint4*>(sm + SM_ALO + off) = lo;
                } else {
                    uint4 z = make_uint4(0, 0, 0, 0);
                    *reinterpret_cast<uint4*>(sm + SM_AHI + off) = z;
                    *reinterpret_cast<uint4*>(sm + SM_ALO + off) = z;
                }
            }
            // neigh half (units 16..31): direct packed copy
            {
                int u2 = u + 16;
                uint32_t off = r * 512 + ((u2 ^ (r & 7)) * 16);
                if (node < N) {
                    uint4 hi = reinterpret_cast<const uint4*>(g_nhi)[node * 16 + u];
                    uint4 lo = reinterpret_cast<const uint4*>(g_nlo)[node * 16 + u];
                    *reinterpret_cast<uint4*>(sm + SM_AHI + off) = hi;
                    *reinterpret_cast<uint4*>(sm + SM_ALO + off) = lo;
                } else {
                    uint4 z = make_uint4(0, 0, 0, 0);
                    *reinterpret_cast<uint4*>(sm + SM_AHI + off) = z;
                    *reinterpret_cast<uint4*>(sm + SM_ALO + off) = z;
                }
            }
        }
        __syncthreads();

        float d[4][4];
#pragma unroll
        for (int t = 0; t < 4; t++)
#pragma unroll
            for (int i = 0; i < 4; i++) d[t][i] = 0.f;

#pragma unroll
        for (int pass = 0; pass < 3; pass++) {
            const uint32_t Ab = sb + ((pass == 2) ? SM_ALO : SM_AHI);
            const uint32_t Wb = sb + ((pass == 1) ? SM_WLO : SM_WHI);
#pragma unroll
            for (int kq = 0; kq < 16; kq++) {
                uint32_t a[4], b[2][4];
                uint32_t ua = (uint32_t)(((2 * kq + lh) ^ l7) * 16);
                uint32_t ub = (uint32_t)(((2 * kq + bkh) ^ l7) * 16);
                ldsm4(a[0], a[1], a[2], a[3], Ab + rowA + ua);
#pragma unroll
                for (int gi = 0; gi < 2; gi++)
                    ldsm4(b[gi][0], b[gi][1], b[gi][2], b[gi][3],
                          Wb + rowB[gi] + ub);
                mma16816(d[0], a[0], a[1], a[2], a[3], b[0][0], b[0][1]);
                mma16816(d[1], a[0], a[1], a[2], a[3], b[0][2], b[0][3]);
                mma16816(d[2], a[0], a[1], a[2], a[3], b[1][0], b[1][1]);
                mma16816(d[3], a[0], a[1], a[2], a[3], b[1][2], b[1][3]);
            }
        }

        // ---- Epilogue: bias + ReLU + store + BN stats ----
        {
            int r0g = row0 + wm * 16 + (lane >> 2);
            int r1g = r0g + 8;
            bool v0 = r0g < N, v1 = r1g < N;
#pragma unroll
            for (int t = 0; t < 4; t++) {
                int cb = wn * 32 + t * 8 + (lane & 3) * 2;
                float x0 = fmaxf(d[t][0] + s_bc[cb],     0.f);
                float x1 = fmaxf(d[t][1] + s_bc[cb + 1], 0.f);
                float x2 = fmaxf(d[t][2] + s_bc[cb],     0.f);
                float x3 = fmaxf(d[t][3] + s_bc[cb + 1], 0.f);
                if (v0) {
                    *reinterpret_cast<float2*>(&out[(size_t)r0g * DF + cb]) =
                        make_float2(x0, x1);
                    st_s[t * 2]     += x0; st_q[t * 2]     += x0 * x0;
                    st_s[t * 2 + 1] += x1; st_q[t * 2 + 1] += x1 * x1;
                }
                if (v1) {
                    *reinterpret_cast<float2*>(&out[(size_t)r1g * DF + cb]) =
                        make_float2(x2, x3);
                    st_s[t * 2]     += x2; st_q[t * 2]     += x2 * x2;
                    st_s[t * 2 + 1] += x3; st_q[t * 2 + 1] += x3 * x3;
                }
            }
        }
    }

    // ---- Flush BN stats: registers -> shared -> global ----
#pragma unroll
    for (int t = 0; t < 4; t++)
#pragma unroll
        for (int c = 0; c < 2; c++) {
            int col = wn * 32 + t * 8 + (lane & 3) * 2 + c;
            atomicAdd(&s_ssum[col], st_s[t * 2 + c]);
            atomicAdd(&s_ssq[col], st_q[t * 2 + c]);
        }
    __syncthreads();
    if (tid < DF) {
        atomicAdd(&g_sum[tid], s_ssum[tid]);
        atomicAdd(&g_sumsq[tid], s_ssq[tid]);
    }

    // ---- Grid-wide barrier (148 blocks, 1/SM resident) ----
    __threadfence();
    __syncthreads();
    if (tid == 0) {
        atomicAdd(&g_bar, 1u);
        while (atomicAdd(&g_bar, 0u) < (unsigned)gridDim.x) __nanosleep(64);
    }
    __syncthreads();
    __threadfence();

    // ---- BN scale/shift (reuse ssum/ssq smem) ----
    if (tid < DF) {
        float invn = 1.0f / (float)N;
        float mu = __ldcg(&g_sum[tid]) * invn;
        float var = __ldcg(&g_sumsq[tid]) * invn - mu * mu;
        float rs = rsqrtf(var + 1e-5f);
        float s = gamma[tid] * rs;
        s_ssum[tid] = s;
        s_ssq[tid] = beta[tid] - mu * s;
    }
    __syncthreads();

    for (int tile = blockIdx.x; tile < ntiles; tile += gridDim.x) {
        const int row0 = tile * TILE_M;
        const int rows = min(TILE_M, N - row0);
        for (int idx = tid; idx < rows * 32; idx += NTHREADS) {
            int r = idx >> 5;
            int c4 = (idx & 31) * 4;
            float4* p = reinterpret_cast<float4*>(
                &out[(size_t)(row0 + r) * DF + c4]);
            float4 v = *p;
            float4 s = *reinterpret_cast<float4*>(&s_ssum[c4]);
            float4 h = *reinterpret_cast<float4*>(&s_ssq[c4]);
            v.x = v.x * s.x + h.x;
            v.y = v.y * s.y + h.y;
            v.z = v.z * s.z + h.z;
            v.w = v.w * s.w + h.w;
            *p = v;
        }
    }
}

// ===========================================================================
// Launch
// ===========================================================================
extern "C" void kernel_launch(void* const* d_in, const int* in_sizes, int n_in,
                              void* d_out, int out_size) {
    const float* feat   = (const float*)d_in[0];
    const int*   src    = (const int*)  d_in[1];
    const int*   dst    = (const int*)  d_in[2];
    const float* ew     = (const float*)d_in[3];
    const float* Wneigh = (const float*)d_in[4];
    const float* Wself  = (const float*)d_in[5];
    const float* b_self = (const float*)d_in[6];
    const float* bias   = (const float*)d_in[7];
    const float* gamma  = (const float*)d_in[8];
    const float* beta   = (const float*)d_in[9];
    float* out = (float*)d_out;

    const int N = in_sizes[0] / DF;
    const int E = in_sizes[1];

    cudaFuncSetAttribute(gemm_kernel,
                         cudaFuncAttributeMaxDynamicSharedMemorySize,
                         SMEM_GEMM_BYTES);

    hist_kernel<<<(E / 4 + 255) / 256, 256>>>(dst, E);
    scan_kernel<<<1, 1024>>>(N);
    scatter_kernel<<<(E + 255) / 256, 256>>>(src, dst, ew, E);
    agg_kernel<<<(N * 32 + 255) / 256, 256>>>(feat, N);
    gemm_kernel<<<GRID_GEMM, NTHREADS, SMEM_GEMM_BYTES>>>(feat, Wneigh, Wself,
                                                          b_self, bias, gamma,
                                                          beta, out, N);
}

// round 16
// speedup vs baseline: 1.6692x; 1.1157x over previous
#include <cuda_runtime.h>
#include <cuda_bf16.h>
#include <cstdint>

#define NMAX 50000
#define NPAD 53248          // 512 * 104
#define EMAX 800000
#define DF   128
#define PREP_GRID 148
#define CHUNK 512           // per-block scan chunk

__device__ int   g_cnt[NPAD];             // zero-init; re-zeroed each prep scatter phase
__device__ int   g_off[NMAX + 4];
__device__ int   g_cur[NMAX + 4];
__device__ int   g_btot[PREP_GRID];
__device__ int2  g_edge[EMAX];
__device__ uint2 g_nhi[NMAX * 32];        // neigh mean, bf16 hi (4 floats / lane)
__device__ uint2 g_nlo[NMAX * 32];        // neigh mean, bf16 lo residual
__device__ float g_sum[DF];
__device__ float g_sumsq[DF];
__device__ unsigned g_bar;                // gemm grid barrier
__device__ unsigned g_pbar;               // prep grid barrier (monotonic; reset by agg)

// ===========================================================================
// helpers
// ===========================================================================
__device__ __forceinline__ uint32_t smem_u32(const void* p) {
    uint32_t a;
    asm("{ .reg .u64 t; cvta.to.shared.u64 t, %1; cvt.u32.u64 %0, t; }"
        : "=r"(a) : "l"(p));
    return a;
}
__device__ __forceinline__ void ldsm4(uint32_t& r0, uint32_t& r1,
                                      uint32_t& r2, uint32_t& r3, uint32_t addr) {
    asm volatile("ldmatrix.sync.aligned.m8n8.x4.shared.b16 {%0,%1,%2,%3}, [%4];"
                 : "=r"(r0), "=r"(r1), "=r"(r2), "=r"(r3) : "r"(addr));
}
__device__ __forceinline__ void mma16816(float* d, uint32_t a0, uint32_t a1,
                                         uint32_t a2, uint32_t a3,
                                         uint32_t b0, uint32_t b1) {
    asm volatile(
        "mma.sync.aligned.m16n8k16.row.col.f32.bf16.bf16.f32 "
        "{%0,%1,%2,%3}, {%4,%5,%6,%7}, {%8,%9}, {%0,%1,%2,%3};"
        : "+f"(d[0]), "+f"(d[1]), "+f"(d[2]), "+f"(d[3])
        : "r"(a0), "r"(a1), "r"(a2), "r"(a3), "r"(b0), "r"(b1));
}
__device__ __forceinline__ uint32_t packbf2(float a, float b) {
    __nv_bfloat16 h0 = __float2bfloat16_rn(a);
    __nv_bfloat16 h1 = __float2bfloat16_rn(b);
    return (uint32_t)__bfloat16_as_ushort(h0)
         | ((uint32_t)__bfloat16_as_ushort(h1) << 16);
}
__device__ __forceinline__ void cvt8(const float* f, uint4& hi, uint4& lo) {
    uint32_t h[4], l[4];
#pragma unroll
    for (int i = 0; i < 4; i++) {
        __nv_bfloat16 h0 = __float2bfloat16_rn(f[2 * i]);
        __nv_bfloat16 h1 = __float2bfloat16_rn(f[2 * i + 1]);
        h[i] = (uint32_t)__bfloat16_as_ushort(h0)
             | ((uint32_t)__bfloat16_as_ushort(h1) << 16);
        l[i] = packbf2(f[2 * i] - __bfloat162float(h0),
                       f[2 * i + 1] - __bfloat162float(h1));
    }
    hi = make_uint4(h[0], h[1], h[2], h[3]);
    lo = make_uint4(l[0], l[1], l[2], l[3]);
}

// ===========================================================================
// 1) Fused prep: histogram -> distributed scan -> CSR scatter
//    One cooperative launch, 148 blocks, monotonic spin barriers.
// ===========================================================================
__device__ __forceinline__ void prep_bar(unsigned target) {
    __syncthreads();
    __threadfence();
    if (threadIdx.x == 0) {
        atomicAdd(&g_pbar, 1u);
        while (atomicAdd(&g_pbar, 0u) < target) __nanosleep(32);
    }
    __syncthreads();
}

__global__ __launch_bounds__(256, 1)
void prep_kernel(const int* __restrict__ src,
                 const int* __restrict__ dst,
                 const float* __restrict__ ew,
                 int E, int N) {
    const int tid = threadIdx.x;
    const int gtid = blockIdx.x * 256 + tid;
    const int gstride = gridDim.x * 256;
    const int lane = tid & 31, wid = tid >> 5;
    __shared__ int wsum[8];
    __shared__ int s_boff;

    // ---- Phase 1: histogram (g_cnt pre-zeroed) ----
    const int nvec = E >> 2;
    for (int i = gtid; i < nvec; i += gstride) {
        int4 d = *reinterpret_cast<const int4*>(dst + i * 4);
        atomicAdd(&g_cnt[d.x], 1);
        atomicAdd(&g_cnt[d.y], 1);
        atomicAdd(&g_cnt[d.z], 1);
        atomicAdd(&g_cnt[d.w], 1);
    }
    for (int i = nvec * 4 + gtid; i < E; i += gstride) atomicAdd(&g_cnt[dst[i]], 1);
    prep_bar(1u * PREP_GRID);

    // ---- Phase 2: per-block chunk totals ----
    const int base = blockIdx.x * CHUNK;
    int v0 = 0, v1 = 0;
    if (base < NPAD) {
        int2 v = *reinterpret_cast<const int2*>(&g_cnt[base + tid * 2]);
        v0 = v.x; v1 = v.y;
    }
    {
        int s = v0 + v1;
        int x = s;
#pragma unroll
        for (int o = 1; o < 32; o <<= 1) {
            int y = __shfl_up_sync(0xFFFFFFFFu, x, o);
            if (lane >= o) x += y;
        }
        if (lane == 31) wsum[wid] = x;
        __syncthreads();
        if (wid == 0 && lane < 8) {
            int t = wsum[lane];
#pragma unroll
            for (int o = 1; o < 8; o <<= 1) {
                int y = __shfl_up_sync(0xFFu, t, o);
                if (lane >= o) t += y;
            }
            wsum[lane] = t;
        }
        __syncthreads();
        if (tid == 0) g_btot[blockIdx.x] = wsum[7];
        // keep per-thread exclusive-within-block value in x (inclusive) for phase 3
        int warp_excl = (wid == 0) ? 0 : wsum[wid - 1];
        int excl_local = warp_excl + x - (v0 + v1);
        prep_bar(2u * PREP_GRID);

        // ---- Phase 3: block offset + write g_off/g_cur ----
        if (tid < 8) {
            int partial = 0;
            for (int i = tid; i < blockIdx.x; i += 8) partial += g_btot[i];
#pragma unroll
            for (int o = 4; o > 0; o >>= 1)
                partial += __shfl_xor_sync(0xFFu, partial, o);
            if (tid == 0) s_boff = partial;
        }
        if (blockIdx.x == 0) {
            if (tid < DF) { g_sum[tid] = 0.f; g_sumsq[tid] = 0.f; }
            if (tid == 0) { g_bar = 0; g_off[N] = E; }
        }
        __syncthreads();
        int off0 = s_boff + excl_local;
        int off1 = off0 + v0;
        int i0 = base + tid * 2;
        if (i0 < N) { g_off[i0] = off0; g_cur[i0] = off0; }
        if (i0 + 1 < N) { g_off[i0 + 1] = off1; g_cur[i0 + 1] = off1; }
    }
    prep_bar(3u * PREP_GRID);

    // ---- Phase 4: scatter into CSR order + re-zero g_cnt for next launch ----
    for (int i = gtid; i < NPAD; i += gstride) g_cnt[i] = 0;
    for (int i = gtid; i < E; i += gstride) {
        int d = dst[i];
        int pos = atomicAdd(&g_cur[d], 1);
        g_edge[pos] = make_int2(src[i], __float_as_int(ew[i]));
    }
}

// ===========================================================================
// 2) Gather-aggregate: one warp per node, emits packed bf16 hi/lo mean.
//    Also resets the prep barrier counter for the next launch.
// ===========================================================================
__global__ void agg_kernel(const float* __restrict__ feat, int N) {
    if (blockIdx.x == 0 && threadIdx.x == 0) g_pbar = 0;
    int node = (blockIdx.x * blockDim.x + threadIdx.x) >> 5;
    int lane = threadIdx.x & 31;
    if (node >= N) return;
    int beg = g_off[node];
    int end = g_off[node + 1];
    float4 acc = make_float4(0.f, 0.f, 0.f, 0.f);
    float deg = 0.f;
    for (int e = beg; e < end; e++) {
        int2 ed = __ldg(&g_edge[e]);
        float w = __int_as_float(ed.y);
        const float4 v = *reinterpret_cast<const float4*>(
            feat + (size_t)ed.x * DF + lane * 4);
        acc.x = fmaf(v.x, w, acc.x);
        acc.y = fmaf(v.y, w, acc.y);
        acc.z = fmaf(v.z, w, acc.z);
        acc.w = fmaf(v.w, w, acc.w);
        deg += w;
    }
    float inv = 1.0f / (deg + 1e-8f);
    acc.x *= inv; acc.y *= inv; acc.z *= inv; acc.w *= inv;
    uint32_t h0 = packbf2(acc.x, acc.y);
    uint32_t h1 = packbf2(acc.z, acc.w);
    g_nhi[node * 32 + lane] = make_uint2(h0, h1);
    uint32_t l0 = packbf2(acc.x - __bfloat162float(__ushort_as_bfloat16(h0 & 0xFFFF)),
                          acc.y - __bfloat162float(__ushort_as_bfloat16(h0 >> 16)));
    uint32_t l1 = packbf2(acc.z - __bfloat162float(__ushort_as_bfloat16(h1 & 0xFFFF)),
                          acc.w - __bfloat162float(__ushort_as_bfloat16(h1 >> 16)));
    g_nlo[node * 32 + lane] = make_uint2(l0, l1);
}

// ===========================================================================
// 3) Persistent split-bf16 mma.sync GEMM (R13 2x4 layout, 256 threads)
//    + bias + ReLU + BN stats + grid barrier + BN normalize.
// ===========================================================================
#define TILE_M 64
#define GRID_GEMM 148
#define SM_WHI  0
#define SM_WLO  65536
#define SM_AHI  131072
#define SM_ALO  163840
#define SM_BC   196608
#define SM_SSUM 197120
#define SM_SSQ  197632
#define SMEM_GEMM_BYTES 198272

__global__ __launch_bounds__(256, 1)
void gemm_kernel(const float* __restrict__ feat,
                 const float* __restrict__ Wneigh,
                 const float* __restrict__ Wself,
                 const float* __restrict__ b_self,
                 const float* __restrict__ bias,
                 const float* __restrict__ gamma,
                 const float* __restrict__ beta,
                 float* __restrict__ out,
                 int N) {
    extern __shared__ char sm[];
    float* s_bc   = reinterpret_cast<float*>(sm + SM_BC);
    float* s_ssum = reinterpret_cast<float*>(sm + SM_SSUM);
    float* s_ssq  = reinterpret_cast<float*>(sm + SM_SSQ);

    const int tid = threadIdx.x;
    const int lane = tid & 31;
    const int wid = tid >> 5;
    const int wm = wid & 1;
    const int wn = wid >> 1;
    const int l7 = lane & 7;
    const int l15 = lane & 15;
    const int lh = lane >> 4;
    const int bkh = (lane >> 3) & 1;
    const int bn = ((lane >> 4) << 3) | l7;

    const uint32_t sb = smem_u32(sm);

    // ---- W hi/lo fill (once) ----
    for (int idx = tid; idx < 128 * 32; idx += 256) {
        int n = idx >> 5;
        int u = idx & 31;
        int k = u * 8;
        float f[8];
        const float* p = (k < DF) ? (Wself + n * DF + k)
                                  : (Wneigh + n * DF + (k - DF));
        *reinterpret_cast<float4*>(f)     = *reinterpret_cast<const float4*>(p);
        *reinterpret_cast<float4*>(f + 4) = *reinterpret_cast<const float4*>(p + 4);
        uint4 hi, lo;
        cvt8(f, hi, lo);
        uint32_t off = n * 512 + ((u ^ (n & 7)) * 16);
        *reinterpret_cast<uint4*>(sm + SM_WHI + off) = hi;
        *reinterpret_cast<uint4*>(sm + SM_WLO + off) = lo;
    }
    if (tid < DF) {
        s_bc[tid] = __ldg(&b_self[tid]) + __ldg(&bias[tid]);
        s_ssum[tid] = 0.f;
        s_ssq[tid] = 0.f;
    }
    __syncthreads();

    uint32_t rowA[2], rowB[2];
#pragma unroll
    for (int mi = 0; mi < 2; mi++)
        rowA[mi] = (uint32_t)(wm * 32 + mi * 16 + l15) * 512;
#pragma unroll
    for (int gi = 0; gi < 2; gi++)
        rowB[gi] = (uint32_t)(wn * 32 + gi * 16 + bn) * 512;

    float st_s[8], st_q[8];
#pragma unroll
    for (int i = 0; i < 8; i++) { st_s[i] = 0.f; st_q[i] = 0.f; }

    const int ntiles = (N + TILE_M - 1) / TILE_M;

    for (int tile = blockIdx.x; tile < ntiles; tile += gridDim.x) {
        const int row0 = tile * TILE_M;

        __syncthreads();   // prior tile's ldmatrix reads done

        // ---- A tile fill: feat half converts, neigh half raw-copies ----
        for (int idx = tid; idx < TILE_M * 16; idx += 256) {
            int r = idx >> 4;
            int u = idx & 15;
            int node = row0 + r;
            {   // feat half (units 0..15)
                uint32_t off = r * 512 + ((u ^ (r & 7)) * 16);
                if (node < N) {
                    const float* p = feat + (size_t)node * DF + u * 8;
                    float f[8];
                    *reinterpret_cast<float4*>(f)     = *reinterpret_cast<const float4*>(p);
                    *reinterpret_cast<float4*>(f + 4) = *reinterpret_cast<const float4*>(p + 4);
                    uint4 hi, lo;
                    cvt8(f, hi, lo);
                    *reinterpret_cast<uint4*>(sm + SM_AHI + off) = hi;
                    *reinterpret_cast<uint4*>(sm + SM_ALO + off) = lo;
                } else {
                    uint4 z = make_uint4(0, 0, 0, 0);
                    *reinterpret_cast<uint4*>(sm + SM_AHI + off) = z;
                    *reinterpret_cast<uint4*>(sm + SM_ALO + off) = z;
                }
            }
            {   // neigh half (units 16..31): packed copy
                int u2 = u + 16;
                uint32_t off = r * 512 + ((u2 ^ (r & 7)) * 16);
                if (node < N) {
                    uint4 hi = reinterpret_cast<const uint4*>(g_nhi)[node * 16 + u];
                    uint4 lo = reinterpret_cast<const uint4*>(g_nlo)[node * 16 + u];
                    *reinterpret_cast<uint4*>(sm + SM_AHI + off) = hi;
                    *reinterpret_cast<uint4*>(sm + SM_ALO + off) = lo;
                } else {
                    uint4 z = make_uint4(0, 0, 0, 0);
                    *reinterpret_cast<uint4*>(sm + SM_AHI + off) = z;
                    *reinterpret_cast<uint4*>(sm + SM_ALO + off) = z;
                }
            }
        }
        __syncthreads();

        float d[2][4][4];
#pragma unroll
        for (int mi = 0; mi < 2; mi++)
#pragma unroll
            for (int t = 0; t < 4; t++)
#pragma unroll
                for (int i = 0; i < 4; i++) d[mi][t][i] = 0.f;

#pragma unroll
        for (int pass = 0; pass < 3; pass++) {
            const uint32_t Ab = sb + ((pass == 2) ? SM_ALO : SM_AHI);
            const uint32_t Wb = sb + ((pass == 1) ? SM_WLO : SM_WHI);
#pragma unroll
            for (int kq = 0; kq < 16; kq++) {
                uint32_t a[2][4], b[2][4];
                uint32_t ua = (uint32_t)(((2 * kq + lh) ^ l7) * 16);
                uint32_t ub = (uint32_t)(((2 * kq + bkh) ^ l7) * 16);
#pragma unroll
                for (int mi = 0; mi < 2; mi++)
                    ldsm4(a[mi][0], a[mi][1], a[mi][2], a[mi][3],
                          Ab + rowA[mi] + ua);
#pragma unroll
                for (int gi = 0; gi < 2; gi++)
                    ldsm4(b[gi][0], b[gi][1], b[gi][2], b[gi][3],
                          Wb + rowB[gi] + ub);
#pragma unroll
                for (int mi = 0; mi < 2; mi++)
#pragma unroll
                    for (int gi = 0; gi < 2; gi++) {
                        mma16816(d[mi][gi * 2 + 0], a[mi][0], a[mi][1],
                                 a[mi][2], a[mi][3], b[gi][0], b[gi][1]);
                        mma16816(d[mi][gi * 2 + 1], a[mi][0], a[mi][1],
                                 a[mi][2], a[mi][3], b[gi][2], b[gi][3]);
                    }
            }
        }

        // ---- Epilogue: bias + ReLU + store + BN stats ----
#pragma unroll
        for (int mi = 0; mi < 2; mi++) {
            int r0g = row0 + wm * 32 + mi * 16 + (lane >> 2);
            int r1g = r0g + 8;
            bool v0 = r0g < N, v1 = r1g < N;
#pragma unroll
            for (int t = 0; t < 4; t++) {
                int cb = wn * 32 + t * 8 + (lane & 3) * 2;
                float x0 = fmaxf(d[mi][t][0] + s_bc[cb],     0.f);
                float x1 = fmaxf(d[mi][t][1] + s_bc[cb + 1], 0.f);
                float x2 = fmaxf(d[mi][t][2] + s_bc[cb],     0.f);
                float x3 = fmaxf(d[mi][t][3] + s_bc[cb + 1], 0.f);
                if (v0) {
                    *reinterpret_cast<float2*>(&out[(size_t)r0g * DF + cb]) =
                        make_float2(x0, x1);
                    st_s[t * 2]     += x0; st_q[t * 2]     += x0 * x0;
                    st_s[t * 2 + 1] += x1; st_q[t * 2 + 1] += x1 * x1;
                }
                if (v1) {
                    *reinterpret_cast<float2*>(&out[(size_t)r1g * DF + cb]) =
                        make_float2(x2, x3);
                    st_s[t * 2]     += x2; st_q[t * 2]     += x2 * x2;
                    st_s[t * 2 + 1] += x3; st_q[t * 2 + 1] += x3 * x3;
                }
            }
        }
    }

    // ---- Flush BN stats: registers -> shared -> global ----
#pragma unroll
    for (int t = 0; t < 4; t++)
#pragma unroll
        for (int c = 0; c < 2; c++) {
            int col = wn * 32 + t * 8 + (lane & 3) * 2 + c;
            atomicAdd(&s_ssum[col], st_s[t * 2 + c]);
            atomicAdd(&s_ssq[col], st_q[t * 2 + c]);
        }
    __syncthreads();
    if (tid < DF) {
        atomicAdd(&g_sum[tid], s_ssum[tid]);
        atomicAdd(&g_sumsq[tid], s_ssq[tid]);
    }

    // ---- Grid-wide barrier (148 blocks, 1/SM resident) ----
    __threadfence();
    __syncthreads();
    if (tid == 0) {
        atomicAdd(&g_bar, 1u);
        while (atomicAdd(&g_bar, 0u) < (unsigned)gridDim.x) __nanosleep(64);
    }
    __syncthreads();
    __threadfence();

    // ---- BN scale/shift (reuse ssum/ssq smem) ----
    if (tid < DF) {
        float invn = 1.0f / (float)N;
        float mu = __ldcg(&g_sum[tid]) * invn;
        float var = __ldcg(&g_sumsq[tid]) * invn - mu * mu;
        float rs = rsqrtf(var + 1e-5f);
        float s = gamma[tid] * rs;
        s_ssum[tid] = s;
        s_ssq[tid] = beta[tid] - mu * s;
    }
    __syncthreads();

    for (int tile = blockIdx.x; tile < ntiles; tile += gridDim.x) {
        const int row0 = tile * TILE_M;
        const int rows = min(TILE_M, N - row0);
        for (int idx = tid; idx < rows * 32; idx += 256) {
            int r = idx >> 5;
            int c4 = (idx & 31) * 4;
            float4* p = reinterpret_cast<float4*>(
                &out[(size_t)(row0 + r) * DF + c4]);
            float4 v = *p;
            float4 s = *reinterpret_cast<float4*>(&s_ssum[c4]);
            float4 h = *reinterpret_cast<float4*>(&s_ssq[c4]);
            v.x = v.x * s.x + h.x;
            v.y = v.y * s.y + h.y;
            v.z = v.z * s.z + h.z;
            v.w = v.w * s.w + h.w;
            *p = v;
        }
    }
}

// ===========================================================================
// Launch
// ===========================================================================
extern "C" void kernel_launch(void* const* d_in, const int* in_sizes, int n_in,
                              void* d_out, int out_size) {
    const float* feat   = (const float*)d_in[0];
    const int*   src    = (const int*)  d_in[1];
    const int*   dst    = (const int*)  d_in[2];
    const float* ew     = (const float*)d_in[3];
    const float* Wneigh = (const float*)d_in[4];
    const float* Wself  = (const float*)d_in[5];
    const float* b_self = (const float*)d_in[6];
    const float* bias   = (const float*)d_in[7];
    const float* gamma  = (const float*)d_in[8];
    const float* beta   = (const float*)d_in[9];
    float* out = (float*)d_out;

    const int N = in_sizes[0] / DF;
    const int E = in_sizes[1];

    cudaFuncSetAttribute(gemm_kernel,
                         cudaFuncAttributeMaxDynamicSharedMemorySize,
                         SMEM_GEMM_BYTES);

    prep_kernel<<<PREP_GRID, 256>>>(src, dst, ew, E, N);
    agg_kernel<<<(N * 32 + 255) / 256, 256>>>(feat, N);
    gemm_kernel<<<GRID_GEMM, 256, SMEM_GEMM_BYTES>>>(feat, Wneigh, Wself, b_self,
                                                     bias, gamma, beta, out, N);
}